// round 13
// baseline (speedup 1.0000x reference)
#include <cuda_runtime.h>
#include <cuda.h>
#include <cuda_bf16.h>
#include <math.h>
#include <stdint.h>

// Problem constants
#define CC   512
#define HWN  4096
#define BB   8
#define GG   32
#define CPG  16
#define EPSF 1e-6f
#define ALPHAF 0.044194173824159216f
#define ALPHA_LOG2E 0.06376059f        // ALPHAF * log2(e)

// GEMM tiling: 128x128 tile, 3 stages, 2 CTAs/SM; chunk = 128 BYTES per row
#define BM 128
#define BN 128
#define STAGES 3
#define PITCHB  144
#define STG_BYTES ((BM + BN) * PITCHB) // 36864
#define SMEM_BYTES (STAGES * STG_BYTES)  // 110592
#define TR8_PITCH 144                  // fp8 transpose pitch (bytes, 16-aligned!)
#define TRF_PITCH 132                  // f32 transpose pitch (f32 units)

#define REG_SZ (BB * HWN * CC)
#define NTILES (HWN / BN)              // 32 scores n-tiles

typedef __nv_bfloat16 bf16;
typedef __nv_bfloat162 bf162;

// ---------------------------------------------------------------------------
// Device-global scratch
// ---------------------------------------------------------------------------
__device__ bf16 g_h[BB * HWN * CC];
__device__ bf16 g_qkv[3 * REG_SZ];              // q | k | v row-major [b][n][c]
__device__ uint8_t g_vpt8[REG_SZ];              // V' = V@Wo^T transposed, e4m3
__device__ uint8_t g_s8[(size_t)BB * HWN * HWN]; // unnorm probs e4m3 (128MB)
__device__ bf16 g_w[4 * CC * CC];               // wq|wk|wv|wo
__device__ float g_bqkv[3 * CC];
__device__ float g_psum[(size_t)BB * NTILES * HWN];
__device__ float g_mu[BB * GG];
__device__ float g_rstd[BB * GG];

// ---------------------------------------------------------------------------
// Helpers
// ---------------------------------------------------------------------------
__device__ __forceinline__ uint32_t smem_u32(const void* p) {
    uint32_t a;
    asm("{ .reg .u64 t; cvta.to.shared.u64 t, %1; cvt.u32.u64 %0, t; }"
        : "=r"(a) : "l"(p));
    return a;
}
__device__ __forceinline__ void cp_async16(uint32_t dst, const void* src) {
    asm volatile("cp.async.cg.shared.global [%0], [%1], 16;" :: "r"(dst), "l"(src));
}
__device__ __forceinline__ void cp_commit() {
    asm volatile("cp.async.commit_group;");
}
__device__ __forceinline__ void mma_bf16(float* d, const uint32_t* a, const uint32_t* b) {
    asm volatile(
        "mma.sync.aligned.m16n8k16.row.col.f32.bf16.bf16.f32 "
        "{%0,%1,%2,%3},{%4,%5,%6,%7},{%8,%9},{%0,%1,%2,%3};"
        : "+f"(d[0]), "+f"(d[1]), "+f"(d[2]), "+f"(d[3])
        : "r"(a[0]), "r"(a[1]), "r"(a[2]), "r"(a[3]), "r"(b[0]), "r"(b[1]));
}
__device__ __forceinline__ void mma_fp8(float* d, const uint32_t* a, const uint32_t* b) {
    asm volatile(
        "mma.sync.aligned.m16n8k32.row.col.f32.e4m3.e4m3.f32 "
        "{%0,%1,%2,%3},{%4,%5,%6,%7},{%8,%9},{%0,%1,%2,%3};"
        : "+f"(d[0]), "+f"(d[1]), "+f"(d[2]), "+f"(d[3])
        : "r"(a[0]), "r"(a[1]), "r"(a[2]), "r"(a[3]), "r"(b[0]), "r"(b[1]));
}
#define LDSM4(r0, r1, r2, r3, addr) \
    asm volatile("ldmatrix.sync.aligned.m8n8.x4.shared.b16 {%0,%1,%2,%3}, [%4];" \
        : "=r"(r0), "=r"(r1), "=r"(r2), "=r"(r3) : "r"(addr))

__device__ __forceinline__ uint32_t pack2(float x, float y) {
    bf162 h = __floats2bfloat162_rn(x, y);
    return *reinterpret_cast<uint32_t*>(&h);
}
// pack (lo, hi) floats -> 2 x e4m3 bytes (lo in byte0)
__device__ __forceinline__ uint16_t pack_e4m3x2(float lo, float hi) {
    uint16_t r;
    asm("cvt.rn.satfinite.e4m3x2.f32 %0, %1, %2;" : "=h"(r) : "f"(hi), "f"(lo));
    return r;
}
__device__ __forceinline__ uint8_t f2e4m3(float x) {
    uint16_t r;
    asm("cvt.rn.satfinite.e4m3x2.f32 %0, %1, %1;" : "=h"(r) : "f"(x));
    return (uint8_t)r;
}

// ---------------------------------------------------------------------------
// Shared mainloop: 128x128 output tile, chunk = 128 bytes of K per row.
// FP8=0: bf16 (chunk = 64 elems, mma k16); FP8=1: e4m3 (chunk = 128, mma k32).
// Byte-level smem layout and ldmatrix addressing identical for both.
// ldaB/ldbB are row strides in BYTES.
// ---------------------------------------------------------------------------
struct Frag { float acc[4][4][4]; };

template <int FP8>
__device__ __forceinline__ void gemm_mainloop(
    const uint8_t* __restrict__ A, const uint8_t* __restrict__ Bm,
    int m0, int n0, size_t ldaB, size_t ldbB, int NC,
    uint32_t smem_base, const uint32_t* aoff, const uint32_t* boff,
    int tid, Frag& f)
{
    #pragma unroll
    for (int mt = 0; mt < 4; mt++)
        #pragma unroll
        for (int nt = 0; nt < 4; nt++)
            #pragma unroll
            for (int c = 0; c < 4; c++) f.acc[mt][nt][c] = 0.f;

    #pragma unroll
    for (int s = 0; s < STAGES - 1; s++) {
        const int k0 = s * 128;
        const uint32_t sb = smem_base + s * STG_BYTES;
        #pragma unroll
        for (int i = 0; i < 4; i++) {
            int idx = i * 256 + tid;
            int row = idx >> 3, kq = idx & 7;
            cp_async16(sb + row * PITCHB + kq * 16,
                       A + (size_t)(m0 + row) * ldaB + k0 + kq * 16);
        }
        #pragma unroll
        for (int i = 0; i < 4; i++) {
            int idx = i * 256 + tid;
            int row = idx >> 3, kq = idx & 7;
            cp_async16(sb + BM * PITCHB + row * PITCHB + kq * 16,
                       Bm + (size_t)(n0 + row) * ldbB + k0 + kq * 16);
        }
        cp_commit();
    }

    for (int c = 0; c < NC; c++) {
        asm volatile("cp.async.wait_group %0;" :: "n"(STAGES - 2));
        __syncthreads();

        const int pf = c + STAGES - 1;
        if (pf < NC) {
            const int k0 = pf * 128;
            const uint32_t sb = smem_base + (pf % STAGES) * STG_BYTES;
            #pragma unroll
            for (int i = 0; i < 4; i++) {
                int idx = i * 256 + tid;
                int row = idx >> 3, kq = idx & 7;
                cp_async16(sb + row * PITCHB + kq * 16,
                           A + (size_t)(m0 + row) * ldaB + k0 + kq * 16);
            }
            #pragma unroll
            for (int i = 0; i < 4; i++) {
                int idx = i * 256 + tid;
                int row = idx >> 3, kq = idx & 7;
                cp_async16(sb + BM * PITCHB + row * PITCHB + kq * 16,
                           Bm + (size_t)(n0 + row) * ldbB + k0 + kq * 16);
            }
            cp_commit();
        }

        const uint32_t sb = smem_base + (c % STAGES) * STG_BYTES;
        #pragma unroll
        for (int ks = 0; ks < 4; ks++) {
            const uint32_t kb = sb + ks * 32;
            uint32_t af[4][4];
            #pragma unroll
            for (int mt = 0; mt < 4; mt++)
                LDSM4(af[mt][0], af[mt][1], af[mt][2], af[mt][3], kb + aoff[mt]);
            uint32_t bfm[4][2];
            #pragma unroll
            for (int p = 0; p < 2; p++)
                LDSM4(bfm[2 * p][0], bfm[2 * p][1], bfm[2 * p + 1][0], bfm[2 * p + 1][1],
                      kb + boff[p]);
            #pragma unroll
            for (int mt = 0; mt < 4; mt++)
                #pragma unroll
                for (int nt = 0; nt < 4; nt++) {
                    if (FP8) mma_fp8(f.acc[mt][nt], af[mt], bfm[nt]);
                    else     mma_bf16(f.acc[mt][nt], af[mt], bfm[nt]);
                }
        }
    }
}

#define THREAD_IDS \
    const int tid = threadIdx.x; \
    const int wid = tid >> 5; \
    const int lane = tid & 31; \
    const int g = lane >> 2; \
    const int kin = lane & 3; \
    const int wm = wid & 1; \
    const int wn = wid >> 1; \
    const int lq = lane >> 3; \
    const int lr = lane & 7; \
    uint32_t aoff[4], boff[2]; \
    _Pragma("unroll") \
    for (int mt = 0; mt < 4; mt++) \
        aoff[mt] = (uint32_t)((wm * 64 + mt * 16 + (lq & 1) * 8 + lr) * PITCHB \
                              + (lq >> 1) * 16); \
    _Pragma("unroll") \
    for (int p = 0; p < 2; p++) \
        boff[p] = (uint32_t)(BM * PITCHB \
                             + (wn * 32 + (2 * p + (lq >> 1)) * 8 + lr) * PITCHB \
                             + (lq & 1) * 16);

// ---------------------------------------------------------------------------
// Merged scores + V' kernel (bf16 mainloop).
//   blockIdx.x < 32 : scores tile -> exp2 -> e4m3 store + psum
//   blockIdx.x >= 32: V' tile -> e4m3 transposed store
// ---------------------------------------------------------------------------
__global__ void __launch_bounds__(256, 2)
score_vp_kernel()
{
    extern __shared__ char smem[];
    const uint32_t smem_base = smem_u32(smem);
    THREAD_IDS;

    const int z = blockIdx.z;
    const bool is_vp = (blockIdx.x >= NTILES);
    const int m0 = blockIdx.y * BM;
    int n0;
    const uint8_t *A, *Bm;
    if (!is_vp) {
        n0 = blockIdx.x * BN;
        A  = (const uint8_t*)(g_qkv + (size_t)z * HWN * CC);
        Bm = (const uint8_t*)(g_qkv + REG_SZ + (size_t)z * HWN * CC);
    } else {
        n0 = (blockIdx.x - NTILES) * BN;
        A  = (const uint8_t*)(g_qkv + 2 * (size_t)REG_SZ + (size_t)z * HWN * CC);
        Bm = (const uint8_t*)(g_w + 3 * CC * CC);
    }

    Frag f;
    gemm_mainloop<0>(A, Bm, m0, n0, CC * 2, CC * 2, 8, smem_base, aoff, boff, tid, f);

    if (!is_vp) {
        uint8_t* Cout = g_s8 + (size_t)z * HWN * HWN;
        __syncthreads();
        float (*sm)[5] = (float(*)[5])smem;
        #pragma unroll
        for (int mt = 0; mt < 4; mt++) {
            int rl = wm * 64 + mt * 16 + g;
            int r0 = m0 + rl;
            float s0 = 0.f, s1 = 0.f;
            #pragma unroll
            for (int nt = 0; nt < 4; nt++) {
                int ch = n0 + wn * 32 + nt * 8 + kin * 2;
                float e0 = exp2f(ALPHA_LOG2E * f.acc[mt][nt][0]);
                float e1 = exp2f(ALPHA_LOG2E * f.acc[mt][nt][1]);
                float e2 = exp2f(ALPHA_LOG2E * f.acc[mt][nt][2]);
                float e3 = exp2f(ALPHA_LOG2E * f.acc[mt][nt][3]);
                *(uint16_t*)(Cout + (size_t)r0 * HWN + ch) = pack_e4m3x2(e0, e1);
                *(uint16_t*)(Cout + (size_t)(r0 + 8) * HWN + ch) = pack_e4m3x2(e2, e3);
                s0 += e0 + e1;
                s1 += e2 + e3;
            }
            s0 += __shfl_xor_sync(0xffffffffu, s0, 1);
            s0 += __shfl_xor_sync(0xffffffffu, s0, 2);
            s1 += __shfl_xor_sync(0xffffffffu, s1, 1);
            s1 += __shfl_xor_sync(0xffffffffu, s1, 2);
            if (kin == 0) {
                sm[rl][wn] = s0;
                sm[rl + 8][wn] = s1;
            }
        }
        __syncthreads();
        if (tid < 128) {
            float t = sm[tid][0] + sm[tid][1] + sm[tid][2] + sm[tid][3];
            g_psum[((size_t)z * NTILES + blockIdx.x) * HWN + m0 + tid] = t;
        }
    } else {
        // V' transposed e4m3 store -> g_vpt8[z][ch][tok]
        __syncthreads();
        uint8_t* tr = (uint8_t*)smem;
        #pragma unroll
        for (int mt = 0; mt < 4; mt++) {
            int tok = wm * 64 + mt * 16 + g;
            #pragma unroll
            for (int nt = 0; nt < 4; nt++) {
                int cl = wn * 32 + nt * 8 + kin * 2;
                tr[(cl    ) * TR8_PITCH + tok    ] = f2e4m3(f.acc[mt][nt][0]);
                tr[(cl + 1) * TR8_PITCH + tok    ] = f2e4m3(f.acc[mt][nt][1]);
                tr[(cl    ) * TR8_PITCH + tok + 8] = f2e4m3(f.acc[mt][nt][2]);
                tr[(cl + 1) * TR8_PITCH + tok + 8] = f2e4m3(f.acc[mt][nt][3]);
            }
        }
        __syncthreads();
        #pragma unroll
        for (int i = 0; i < 4; i++) {
            int idx = i * 256 + tid;
            int cl = idx >> 3, t16 = (idx & 7) * 16;
            uint4 v = *(uint4*)&tr[cl * TR8_PITCH + t16];
            *(uint4*)(g_vpt8 + ((size_t)z * CC + n0 + cl) * HWN + m0 + t16) = v;
        }
    }
}

// ---------------------------------------------------------------------------
// QKV kernel (bf16): C = h @ [wq|wk|wv]^T + bias, row-major bf16
// ---------------------------------------------------------------------------
__global__ void __launch_bounds__(256, 2)
qkv_kernel()
{
    extern __shared__ char smem[];
    const uint32_t smem_base = smem_u32(smem);
    THREAD_IDS;

    const int m0 = blockIdx.y * BM;
    const int n0 = blockIdx.x * BN;        // 0..1535

    Frag f;
    gemm_mainloop<0>((const uint8_t*)g_h, (const uint8_t*)g_w, m0, n0,
                     CC * 2, CC * 2, 8, smem_base, aoff, boff, tid, f);

    const int which = n0 >> 9;
    bf16* Cout = g_qkv + (size_t)which * REG_SZ;
    const int nsub0 = n0 & 511;
    #pragma unroll
    for (int mt = 0; mt < 4; mt++) {
        int r0 = m0 + wm * 64 + mt * 16 + g;
        #pragma unroll
        for (int nt = 0; nt < 4; nt++) {
            int cl = wn * 32 + nt * 8 + kin * 2;
            float b0 = g_bqkv[n0 + cl], b1 = g_bqkv[n0 + cl + 1];
            int ch = nsub0 + cl;
            *(bf162*)(Cout + (size_t)r0 * CC + ch) =
                __floats2bfloat162_rn(f.acc[mt][nt][0] + b0, f.acc[mt][nt][1] + b1);
            *(bf162*)(Cout + (size_t)(r0 + 8) * CC + ch) =
                __floats2bfloat162_rn(f.acc[mt][nt][2] + b0, f.acc[mt][nt][3] + b1);
        }
    }
}

// ---------------------------------------------------------------------------
// SV final kernel (FP8 mainloop): out = (P @ V')*rinv + bo + resid, f32 [b][c][hw]
// A = g_s8 (K=4096 e4m3), B = g_vpt8 (K-major e4m3)
// ---------------------------------------------------------------------------
__global__ void __launch_bounds__(256, 2)
sv_kernel(const float* __restrict__ bias, const float* __restrict__ resid,
          float* __restrict__ Cout)
{
    extern __shared__ char smem[];
    const uint32_t smem_base = smem_u32(smem);
    THREAD_IDS;

    const int z = blockIdx.z;
    const int m0 = blockIdx.y * BM;
    const int n0 = blockIdx.x * BN;
    const uint8_t* A  = g_s8 + (size_t)z * HWN * HWN;
    const uint8_t* Bm = g_vpt8 + (size_t)z * CC * HWN;

    Frag f;
    gemm_mainloop<1>(A, Bm, m0, n0, HWN, HWN, HWN / 128, smem_base, aoff, boff, tid, f);

    __syncthreads();
    float* rsh = (float*)smem;
    if (tid < 128) {
        const float* p = g_psum + (size_t)z * NTILES * HWN + m0 + tid;
        float s = 0.f;
        #pragma unroll
        for (int t = 0; t < NTILES; t++) s += p[(size_t)t * HWN];
        rsh[tid] = 1.f / s;
    }
    __syncthreads();
    float iv[4][2];
    #pragma unroll
    for (int mt = 0; mt < 4; mt++) {
        int rl = wm * 64 + mt * 16 + g;
        iv[mt][0] = rsh[rl];
        iv[mt][1] = rsh[rl + 8];
    }
    __syncthreads();
    float* tr = (float*)smem;
    #pragma unroll
    for (int mt = 0; mt < 4; mt++) {
        int tok = wm * 64 + mt * 16 + g;
        #pragma unroll
        for (int nt = 0; nt < 4; nt++) {
            int ch = wn * 32 + nt * 8 + kin * 2;
            tr[(ch    ) * TRF_PITCH + tok    ] = f.acc[mt][nt][0] * iv[mt][0];
            tr[(ch + 1) * TRF_PITCH + tok    ] = f.acc[mt][nt][1] * iv[mt][0];
            tr[(ch    ) * TRF_PITCH + tok + 8] = f.acc[mt][nt][2] * iv[mt][1];
            tr[(ch + 1) * TRF_PITCH + tok + 8] = f.acc[mt][nt][3] * iv[mt][1];
        }
    }
    __syncthreads();
    #pragma unroll
    for (int i = 0; i < 16; i++) {
        int idx = i * 256 + tid;
        int ch = idx >> 5, t4 = (idx & 31) * 4;
        float4 v = *(float4*)&tr[ch * TRF_PITCH + t4];
        float bv = bias[n0 + ch];
        v.x += bv; v.y += bv; v.z += bv; v.w += bv;
        size_t oidx = ((size_t)z * CC + n0 + ch) * HWN + m0 + t4;
        float4 rr = *(const float4*)(resid + oidx);
        v.x += rr.x; v.y += rr.y; v.z += rr.z; v.w += rr.w;
        *(float4*)(Cout + oidx) = v;
    }
}

// ---------------------------------------------------------------------------
// Prep kernel: weights->bf16 (blocks 0..1023), biases (1024..1029),
// GN stats (1030..1285)
// ---------------------------------------------------------------------------
__global__ void prep_kernel(const float* __restrict__ wq, const float* __restrict__ wk,
                            const float* __restrict__ wv, const float* __restrict__ wo,
                            const float* __restrict__ bq, const float* __restrict__ bk,
                            const float* __restrict__ bv, const float* __restrict__ x) {
    __shared__ float sh1[256], sh2[256];
    const int blk = blockIdx.x;
    if (blk < 1024) {
        int i = (blk * 256 + threadIdx.x) * 4;
        int w = i >> 18;
        const float* s = (w == 0) ? wq : (w == 1) ? wk : (w == 2) ? wv : wo;
        float4 v = *(const float4*)(s + (i & (CC * CC - 1)));
        uint2 o;
        o.x = pack2(v.x, v.y);
        o.y = pack2(v.z, v.w);
        *(uint2*)(g_w + i) = o;
    } else if (blk < 1030) {
        int i = (blk - 1024) * 256 + threadIdx.x;
        const float* src = (i < CC) ? bq : (i < 2 * CC) ? bk : bv;
        g_bqkv[i] = src[i & (CC - 1)];
    } else {
        const int bg = blk - 1030;
        const int b = bg / GG, g = bg % GG;
        const float4* xp = (const float4*)(x + ((size_t)b * CC + (size_t)g * CPG) * HWN);
        float s = 0.f, ss = 0.f;
        #pragma unroll 4
        for (int i = threadIdx.x; i < CPG * HWN / 4; i += 256) {
            float4 v = xp[i];
            s  += v.x + v.y + v.z + v.w;
            ss += v.x * v.x + v.y * v.y + v.z * v.z + v.w * v.w;
        }
        sh1[threadIdx.x] = s; sh2[threadIdx.x] = ss;
        __syncthreads();
        for (int o = 128; o > 0; o >>= 1) {
            if (threadIdx.x < o) {
                sh1[threadIdx.x] += sh1[threadIdx.x + o];
                sh2[threadIdx.x] += sh2[threadIdx.x + o];
            }
            __syncthreads();
        }
        if (threadIdx.x == 0) {
            const float inv_n = 1.f / (CPG * HWN);
            float mu = sh1[0] * inv_n;
            float var = sh2[0] * inv_n - mu * mu;
            g_mu[bg] = mu;
            g_rstd[bg] = rsqrtf(var + EPSF);
        }
    }
}

// ---------------------------------------------------------------------------
// Normalize + transpose -> h[b][n][c] bf16
// ---------------------------------------------------------------------------
__global__ void gn_norm_t_kernel(const float* __restrict__ x,
                                 const float* __restrict__ gamma,
                                 const float* __restrict__ beta) {
    __shared__ float tile[32][33];
    const int b = blockIdx.z;
    const int n0 = blockIdx.x * 32;
    const int c0 = blockIdx.y * 32;
    #pragma unroll
    for (int i = 0; i < 4; i++) {
        int c = c0 + threadIdx.y + i * 8;
        int n = n0 + threadIdx.x;
        float v = x[((size_t)b * CC + c) * HWN + n];
        int gidx = b * GG + (c / CPG);
        v = (v - g_mu[gidx]) * g_rstd[gidx] * gamma[c] + beta[c];
        tile[threadIdx.y + i * 8][threadIdx.x] = v;
    }
    __syncthreads();
    #pragma unroll
    for (int i = 0; i < 4; i++) {
        int n = n0 + threadIdx.y + i * 8;
        int c = c0 + threadIdx.x;
        g_h[((size_t)b * HWN + n) * CC + c] =
            __float2bfloat16_rn(tile[threadIdx.x][threadIdx.y + i * 8]);
    }
}

// ---------------------------------------------------------------------------
// Launch
// ---------------------------------------------------------------------------
extern "C" void kernel_launch(void* const* d_in, const int* in_sizes, int n_in,
                              void* d_out, int out_size) {
    const float* x     = (const float*)d_in[0];
    const float* gamma = (const float*)d_in[1];
    const float* beta  = (const float*)d_in[2];
    const float* wq    = (const float*)d_in[3];
    const float* bq    = (const float*)d_in[4];
    const float* wk    = (const float*)d_in[5];
    const float* bk    = (const float*)d_in[6];
    const float* wv    = (const float*)d_in[7];
    const float* bv    = (const float*)d_in[8];
    const float* wo    = (const float*)d_in[9];
    const float* bo    = (const float*)d_in[10];
    float* out = (float*)d_out;

    cudaFuncSetAttribute(qkv_kernel, cudaFuncAttributeMaxDynamicSharedMemorySize, SMEM_BYTES);
    cudaFuncSetAttribute(score_vp_kernel, cudaFuncAttributeMaxDynamicSharedMemorySize, SMEM_BYTES);
    cudaFuncSetAttribute(sv_kernel, cudaFuncAttributeMaxDynamicSharedMemorySize, SMEM_BYTES);

    // 0) prep: weights->bf16, biases, GN stats (single launch)
    prep_kernel<<<1030 + BB * GG, 256>>>(wq, wk, wv, wo, bq, bk, bv, x);

    // 1) normalize + transpose
    gn_norm_t_kernel<<<dim3(HWN / 32, CC / 32, BB), dim3(32, 8)>>>(x, gamma, beta);

    // 2) fused QKV projection
    qkv_kernel<<<dim3(3 * CC / BN, BB * HWN / BM, 1), 256, SMEM_BYTES>>>();

    // 3) merged: scores (+exp2 -> e4m3, +psum)  AND  V' = V@Wo^T (e4m3, transposed)
    score_vp_kernel<<<dim3(NTILES + CC / BN, HWN / BM, BB), 256, SMEM_BYTES>>>();

    // 4) out = (P @ V')*rinv + bo + resid -> f32 [b][c][hw]   (fp8 tensor cores)
    sv_kernel<<<dim3(CC / BN, HWN / BM, BB), 256, SMEM_BYTES>>>(bo, x, out);
}

// round 14
// speedup vs baseline: 1.0420x; 1.0420x over previous
#include <cuda_runtime.h>
#include <cuda.h>
#include <cuda_bf16.h>
#include <math.h>
#include <stdint.h>

// Problem constants
#define CC   512
#define HWN  4096
#define BB   8
#define GG   32
#define CPG  16
#define EPSF 1e-6f
#define ALPHAF 0.044194173824159216f
#define ALPHA_LOG2E 0.06376059f        // ALPHAF * log2(e)

// GEMM tiling (bf16): 128x128 tile, 3 stages, 2 CTAs/SM  (best-known config)
#define BM 128
#define BN 128
#define KC 64
#define STAGES 3
#define PITCHB  144
#define STG_BYTES ((BM + BN) * PITCHB) // 36864
#define SMEM_BYTES (STAGES * STG_BYTES)  // 110592
#define TRB_PITCH 136
#define TRF_PITCH 132

#define REG_SZ (BB * HWN * CC)
#define NTILES (HWN / BN)              // 32 scores n-tiles

typedef __nv_bfloat16 bf16;
typedef __nv_bfloat162 bf162;

// ---------------------------------------------------------------------------
// Device-global scratch
// ---------------------------------------------------------------------------
__device__ bf16 g_h[BB * HWN * CC];
__device__ bf16 g_qkv[3 * REG_SZ];             // q | k | v row-major [b][n][c]
__device__ bf16 g_vpt[REG_SZ];                 // V' = V@Wo^T transposed [b][c][n]
__device__ bf16 g_s[(size_t)BB * HWN * HWN];   // unnorm probs (256MB)
__device__ bf16 g_w[4 * CC * CC];              // wq|wk|wv|wo
__device__ float g_bqkv[3 * CC];
__device__ float g_psum[(size_t)BB * NTILES * HWN];
__device__ float g_mu[BB * GG];
__device__ float g_rstd[BB * GG];

// ---------------------------------------------------------------------------
// Helpers
// ---------------------------------------------------------------------------
__device__ __forceinline__ uint32_t smem_u32(const void* p) {
    uint32_t a;
    asm("{ .reg .u64 t; cvta.to.shared.u64 t, %1; cvt.u32.u64 %0, t; }"
        : "=r"(a) : "l"(p));
    return a;
}
__device__ __forceinline__ void cp_async16(uint32_t dst, const void* src) {
    asm volatile("cp.async.cg.shared.global [%0], [%1], 16;" :: "r"(dst), "l"(src));
}
__device__ __forceinline__ void cp_commit() {
    asm volatile("cp.async.commit_group;");
}
__device__ __forceinline__ void mma_bf16(float* d, const uint32_t* a, const uint32_t* b) {
    asm volatile(
        "mma.sync.aligned.m16n8k16.row.col.f32.bf16.bf16.f32 "
        "{%0,%1,%2,%3},{%4,%5,%6,%7},{%8,%9},{%0,%1,%2,%3};"
        : "+f"(d[0]), "+f"(d[1]), "+f"(d[2]), "+f"(d[3])
        : "r"(a[0]), "r"(a[1]), "r"(a[2]), "r"(a[3]), "r"(b[0]), "r"(b[1]));
}
#define LDSM4(r0, r1, r2, r3, addr) \
    asm volatile("ldmatrix.sync.aligned.m8n8.x4.shared.b16 {%0,%1,%2,%3}, [%4];" \
        : "=r"(r0), "=r"(r1), "=r"(r2), "=r"(r3) : "r"(addr))

__device__ __forceinline__ uint32_t pack2(float x, float y) {
    bf162 h = __floats2bfloat162_rn(x, y);
    return *reinterpret_cast<uint32_t*>(&h);
}

// ---------------------------------------------------------------------------
// Shared mainloop body (128x128 tile, K-major bf16 operands)
// ---------------------------------------------------------------------------
struct Frag { float acc[4][4][4]; };

__device__ __forceinline__ void gemm_mainloop_512(
    const bf16* __restrict__ A, const bf16* __restrict__ Bm,
    int m0, int n0, int lda, int ldb, int NC,
    uint32_t smem_base, const uint32_t* aoff, const uint32_t* boff,
    int tid, Frag& f)
{
    #pragma unroll
    for (int mt = 0; mt < 4; mt++)
        #pragma unroll
        for (int nt = 0; nt < 4; nt++)
            #pragma unroll
            for (int c = 0; c < 4; c++) f.acc[mt][nt][c] = 0.f;

    #pragma unroll
    for (int s = 0; s < STAGES - 1; s++) {
        const int k0 = s * KC;
        const uint32_t sb = smem_base + s * STG_BYTES;
        #pragma unroll
        for (int i = 0; i < 4; i++) {
            int idx = i * 256 + tid;
            int row = idx >> 3, kq = idx & 7;
            cp_async16(sb + row * PITCHB + kq * 16,
                       A + (size_t)(m0 + row) * lda + k0 + kq * 8);
        }
        #pragma unroll
        for (int i = 0; i < 4; i++) {
            int idx = i * 256 + tid;
            int row = idx >> 3, kq = idx & 7;
            cp_async16(sb + BM * PITCHB + row * PITCHB + kq * 16,
                       Bm + (size_t)(n0 + row) * ldb + k0 + kq * 8);
        }
        cp_commit();
    }

    for (int c = 0; c < NC; c++) {
        asm volatile("cp.async.wait_group %0;" :: "n"(STAGES - 2));
        __syncthreads();

        const int pf = c + STAGES - 1;
        if (pf < NC) {
            const int k0 = pf * KC;
            const uint32_t sb = smem_base + (pf % STAGES) * STG_BYTES;
            #pragma unroll
            for (int i = 0; i < 4; i++) {
                int idx = i * 256 + tid;
                int row = idx >> 3, kq = idx & 7;
                cp_async16(sb + row * PITCHB + kq * 16,
                           A + (size_t)(m0 + row) * lda + k0 + kq * 8);
            }
            #pragma unroll
            for (int i = 0; i < 4; i++) {
                int idx = i * 256 + tid;
                int row = idx >> 3, kq = idx & 7;
                cp_async16(sb + BM * PITCHB + row * PITCHB + kq * 16,
                           Bm + (size_t)(n0 + row) * ldb + k0 + kq * 8);
            }
            cp_commit();
        }

        const uint32_t sb = smem_base + (c % STAGES) * STG_BYTES;
        #pragma unroll
        for (int ks = 0; ks < 4; ks++) {
            const uint32_t kb = sb + ks * 32;
            uint32_t af[4][4];
            #pragma unroll
            for (int mt = 0; mt < 4; mt++)
                LDSM4(af[mt][0], af[mt][1], af[mt][2], af[mt][3], kb + aoff[mt]);
            uint32_t bfm[4][2];
            #pragma unroll
            for (int p = 0; p < 2; p++)
                LDSM4(bfm[2 * p][0], bfm[2 * p][1], bfm[2 * p + 1][0], bfm[2 * p + 1][1],
                      kb + boff[p]);
            #pragma unroll
            for (int mt = 0; mt < 4; mt++)
                #pragma unroll
                for (int nt = 0; nt < 4; nt++)
                    mma_bf16(f.acc[mt][nt], af[mt], bfm[nt]);
        }
    }
}

#define THREAD_IDS \
    const int tid = threadIdx.x; \
    const int wid = tid >> 5; \
    const int lane = tid & 31; \
    const int g = lane >> 2; \
    const int kin = lane & 3; \
    const int wm = wid & 1; \
    const int wn = wid >> 1; \
    const int lq = lane >> 3; \
    const int lr = lane & 7; \
    uint32_t aoff[4], boff[2]; \
    _Pragma("unroll") \
    for (int mt = 0; mt < 4; mt++) \
        aoff[mt] = (uint32_t)((wm * 64 + mt * 16 + (lq & 1) * 8 + lr) * PITCHB \
                              + (lq >> 1) * 16); \
    _Pragma("unroll") \
    for (int p = 0; p < 2; p++) \
        boff[p] = (uint32_t)(BM * PITCHB \
                             + (wn * 32 + (2 * p + (lq >> 1)) * 8 + lr) * PITCHB \
                             + (lq & 1) * 16);

// ---------------------------------------------------------------------------
// Merged scores + V' kernel.
//   blockIdx.x < 32 : scores tile  S[z] = exp2(a * Q K^T), psum
//   blockIdx.x >= 32: V' tile      g_vpt[z][ch][tok] = (V @ Wo^T)^T
// ---------------------------------------------------------------------------
__global__ void __launch_bounds__(256, 2)
score_vp_kernel()
{
    extern __shared__ char smem[];
    const uint32_t smem_base = smem_u32(smem);
    THREAD_IDS;

    const int z = blockIdx.z;
    const bool is_vp = (blockIdx.x >= NTILES);
    const int m0 = blockIdx.y * BM;
    int n0;
    const bf16 *A, *Bm;
    if (!is_vp) {
        n0 = blockIdx.x * BN;
        A  = g_qkv + (size_t)z * HWN * CC;
        Bm = g_qkv + REG_SZ + (size_t)z * HWN * CC;
    } else {
        n0 = (blockIdx.x - NTILES) * BN;
        A  = g_qkv + 2 * (size_t)REG_SZ + (size_t)z * HWN * CC;
        Bm = g_w + 3 * CC * CC;
    }

    Frag f;
    gemm_mainloop_512(A, Bm, m0, n0, CC, CC, CC / KC, smem_base, aoff, boff, tid, f);

    if (!is_vp) {
        bf16* Cout = g_s + (size_t)z * HWN * HWN;
        __syncthreads();
        float (*sm)[5] = (float(*)[5])smem;
        #pragma unroll
        for (int mt = 0; mt < 4; mt++) {
            int rl = wm * 64 + mt * 16 + g;
            int r0 = m0 + rl;
            float s0 = 0.f, s1 = 0.f;
            #pragma unroll
            for (int nt = 0; nt < 4; nt++) {
                int ch = n0 + wn * 32 + nt * 8 + kin * 2;
                float e0 = exp2f(ALPHA_LOG2E * f.acc[mt][nt][0]);
                float e1 = exp2f(ALPHA_LOG2E * f.acc[mt][nt][1]);
                float e2 = exp2f(ALPHA_LOG2E * f.acc[mt][nt][2]);
                float e3 = exp2f(ALPHA_LOG2E * f.acc[mt][nt][3]);
                *(bf162*)(Cout + (size_t)r0 * HWN + ch) = __floats2bfloat162_rn(e0, e1);
                *(bf162*)(Cout + (size_t)(r0 + 8) * HWN + ch) = __floats2bfloat162_rn(e2, e3);
                s0 += e0 + e1;
                s1 += e2 + e3;
            }
            s0 += __shfl_xor_sync(0xffffffffu, s0, 1);
            s0 += __shfl_xor_sync(0xffffffffu, s0, 2);
            s1 += __shfl_xor_sync(0xffffffffu, s1, 1);
            s1 += __shfl_xor_sync(0xffffffffu, s1, 2);
            if (kin == 0) {
                sm[rl][wn] = s0;
                sm[rl + 8][wn] = s1;
            }
        }
        __syncthreads();
        if (tid < 128) {
            float t = sm[tid][0] + sm[tid][1] + sm[tid][2] + sm[tid][3];
            g_psum[((size_t)z * NTILES + blockIdx.x) * HWN + m0 + tid] = t;
        }
    } else {
        // V' transposed bf16 store -> g_vpt[z][ch][tok]
        __syncthreads();
        bf16* tr = (bf16*)smem;
        #pragma unroll
        for (int mt = 0; mt < 4; mt++) {
            int tok = wm * 64 + mt * 16 + g;
            #pragma unroll
            for (int nt = 0; nt < 4; nt++) {
                int cl = wn * 32 + nt * 8 + kin * 2;
                tr[(cl    ) * TRB_PITCH + tok    ] = __float2bfloat16_rn(f.acc[mt][nt][0]);
                tr[(cl + 1) * TRB_PITCH + tok    ] = __float2bfloat16_rn(f.acc[mt][nt][1]);
                tr[(cl    ) * TRB_PITCH + tok + 8] = __float2bfloat16_rn(f.acc[mt][nt][2]);
                tr[(cl + 1) * TRB_PITCH + tok + 8] = __float2bfloat16_rn(f.acc[mt][nt][3]);
            }
        }
        __syncthreads();
        #pragma unroll
        for (int i = 0; i < 8; i++) {
            int idx = i * 256 + tid;
            int cl = idx >> 4, t8 = (idx & 15) * 8;
            uint4 v = *(uint4*)&tr[cl * TRB_PITCH + t8];
            *(uint4*)(g_vpt + ((size_t)z * CC + n0 + cl) * HWN + m0 + t8) = v;
        }
    }
}

// ---------------------------------------------------------------------------
// QKV kernel: C = h @ [wq|wk|wv]^T + bias, row-major bf16
// ---------------------------------------------------------------------------
__global__ void __launch_bounds__(256, 2)
qkv_kernel()
{
    extern __shared__ char smem[];
    const uint32_t smem_base = smem_u32(smem);
    THREAD_IDS;

    const int m0 = blockIdx.y * BM;
    const int n0 = blockIdx.x * BN;        // 0..1535

    Frag f;
    gemm_mainloop_512(g_h, g_w, m0, n0, CC, CC, CC / KC, smem_base, aoff, boff, tid, f);

    const int which = n0 >> 9;
    bf16* Cout = g_qkv + (size_t)which * REG_SZ;
    const int nsub0 = n0 & 511;
    #pragma unroll
    for (int mt = 0; mt < 4; mt++) {
        int r0 = m0 + wm * 64 + mt * 16 + g;
        #pragma unroll
        for (int nt = 0; nt < 4; nt++) {
            int cl = wn * 32 + nt * 8 + kin * 2;
            float b0 = g_bqkv[n0 + cl], b1 = g_bqkv[n0 + cl + 1];
            int ch = nsub0 + cl;
            *(bf162*)(Cout + (size_t)r0 * CC + ch) =
                __floats2bfloat162_rn(f.acc[mt][nt][0] + b0, f.acc[mt][nt][1] + b1);
            *(bf162*)(Cout + (size_t)(r0 + 8) * CC + ch) =
                __floats2bfloat162_rn(f.acc[mt][nt][2] + b0, f.acc[mt][nt][3] + b1);
        }
    }
}

// ---------------------------------------------------------------------------
// SV final kernel: out = (P @ V')*rinv + bo + resid, f32 [b][c][hw]
// ---------------------------------------------------------------------------
__global__ void __launch_bounds__(256, 2)
sv_kernel(const float* __restrict__ bias, const float* __restrict__ resid,
          float* __restrict__ Cout)
{
    extern __shared__ char smem[];
    const uint32_t smem_base = smem_u32(smem);
    THREAD_IDS;

    const int z = blockIdx.z;
    const int m0 = blockIdx.y * BM;
    const int n0 = blockIdx.x * BN;
    const bf16* A  = g_s + (size_t)z * HWN * HWN;
    const bf16* Bm = g_vpt + (size_t)z * CC * HWN;

    Frag f;
    gemm_mainloop_512(A, Bm, m0, n0, HWN, HWN, HWN / KC, smem_base, aoff, boff, tid, f);

    __syncthreads();
    float* rsh = (float*)smem;
    if (tid < 128) {
        const float* p = g_psum + (size_t)z * NTILES * HWN + m0 + tid;
        float s = 0.f;
        #pragma unroll
        for (int t = 0; t < NTILES; t++) s += p[(size_t)t * HWN];
        rsh[tid] = 1.f / s;
    }
    __syncthreads();
    float iv[4][2];
    #pragma unroll
    for (int mt = 0; mt < 4; mt++) {
        int rl = wm * 64 + mt * 16 + g;
        iv[mt][0] = rsh[rl];
        iv[mt][1] = rsh[rl + 8];
    }
    __syncthreads();
    float* tr = (float*)smem;
    #pragma unroll
    for (int mt = 0; mt < 4; mt++) {
        int tok = wm * 64 + mt * 16 + g;
        #pragma unroll
        for (int nt = 0; nt < 4; nt++) {
            int ch = wn * 32 + nt * 8 + kin * 2;
            tr[(ch    ) * TRF_PITCH + tok    ] = f.acc[mt][nt][0] * iv[mt][0];
            tr[(ch + 1) * TRF_PITCH + tok    ] = f.acc[mt][nt][1] * iv[mt][0];
            tr[(ch    ) * TRF_PITCH + tok + 8] = f.acc[mt][nt][2] * iv[mt][1];
            tr[(ch + 1) * TRF_PITCH + tok + 8] = f.acc[mt][nt][3] * iv[mt][1];
        }
    }
    __syncthreads();
    #pragma unroll
    for (int i = 0; i < 16; i++) {
        int idx = i * 256 + tid;
        int ch = idx >> 5, t4 = (idx & 31) * 4;
        float4 v = *(float4*)&tr[ch * TRF_PITCH + t4];
        float bv = bias[n0 + ch];
        v.x += bv; v.y += bv; v.z += bv; v.w += bv;
        size_t oidx = ((size_t)z * CC + n0 + ch) * HWN + m0 + t4;
        float4 rr = *(const float4*)(resid + oidx);
        v.x += rr.x; v.y += rr.y; v.z += rr.z; v.w += rr.w;
        *(float4*)(Cout + oidx) = v;
    }
}

// ---------------------------------------------------------------------------
// Prep kernel: weights->bf16 (blocks 0..1023), biases (1024..1029),
// GN stats (1030..1285)
// ---------------------------------------------------------------------------
__global__ void prep_kernel(const float* __restrict__ wq, const float* __restrict__ wk,
                            const float* __restrict__ wv, const float* __restrict__ wo,
                            const float* __restrict__ bq, const float* __restrict__ bk,
                            const float* __restrict__ bv, const float* __restrict__ x) {
    __shared__ float sh1[256], sh2[256];
    const int blk = blockIdx.x;
    if (blk < 1024) {
        int i = (blk * 256 + threadIdx.x) * 4;
        int w = i >> 18;
        const float* s = (w == 0) ? wq : (w == 1) ? wk : (w == 2) ? wv : wo;
        float4 v = *(const float4*)(s + (i & (CC * CC - 1)));
        uint2 o;
        o.x = pack2(v.x, v.y);
        o.y = pack2(v.z, v.w);
        *(uint2*)(g_w + i) = o;
    } else if (blk < 1030) {
        int i = (blk - 1024) * 256 + threadIdx.x;
        const float* src = (i < CC) ? bq : (i < 2 * CC) ? bk : bv;
        g_bqkv[i] = src[i & (CC - 1)];
    } else {
        const int bg = blk - 1030;
        const int b = bg / GG, g = bg % GG;
        const float4* xp = (const float4*)(x + ((size_t)b * CC + (size_t)g * CPG) * HWN);
        float s = 0.f, ss = 0.f;
        #pragma unroll 4
        for (int i = threadIdx.x; i < CPG * HWN / 4; i += 256) {
            float4 v = xp[i];
            s  += v.x + v.y + v.z + v.w;
            ss += v.x * v.x + v.y * v.y + v.z * v.z + v.w * v.w;
        }
        sh1[threadIdx.x] = s; sh2[threadIdx.x] = ss;
        __syncthreads();
        for (int o = 128; o > 0; o >>= 1) {
            if (threadIdx.x < o) {
                sh1[threadIdx.x] += sh1[threadIdx.x + o];
                sh2[threadIdx.x] += sh2[threadIdx.x + o];
            }
            __syncthreads();
        }
        if (threadIdx.x == 0) {
            const float inv_n = 1.f / (CPG * HWN);
            float mu = sh1[0] * inv_n;
            float var = sh2[0] * inv_n - mu * mu;
            g_mu[bg] = mu;
            g_rstd[bg] = rsqrtf(var + EPSF);
        }
    }
}

// ---------------------------------------------------------------------------
// Normalize + transpose -> h[b][n][c] bf16
// ---------------------------------------------------------------------------
__global__ void gn_norm_t_kernel(const float* __restrict__ x,
                                 const float* __restrict__ gamma,
                                 const float* __restrict__ beta) {
    __shared__ float tile[32][33];
    const int b = blockIdx.z;
    const int n0 = blockIdx.x * 32;
    const int c0 = blockIdx.y * 32;
    #pragma unroll
    for (int i = 0; i < 4; i++) {
        int c = c0 + threadIdx.y + i * 8;
        int n = n0 + threadIdx.x;
        float v = x[((size_t)b * CC + c) * HWN + n];
        int gidx = b * GG + (c / CPG);
        v = (v - g_mu[gidx]) * g_rstd[gidx] * gamma[c] + beta[c];
        tile[threadIdx.y + i * 8][threadIdx.x] = v;
    }
    __syncthreads();
    #pragma unroll
    for (int i = 0; i < 4; i++) {
        int n = n0 + threadIdx.y + i * 8;
        int c = c0 + threadIdx.x;
        g_h[((size_t)b * HWN + n) * CC + c] =
            __float2bfloat16_rn(tile[threadIdx.x][threadIdx.y + i * 8]);
    }
}

// ---------------------------------------------------------------------------
// Launch
// ---------------------------------------------------------------------------
extern "C" void kernel_launch(void* const* d_in, const int* in_sizes, int n_in,
                              void* d_out, int out_size) {
    const float* x     = (const float*)d_in[0];
    const float* gamma = (const float*)d_in[1];
    const float* beta  = (const float*)d_in[2];
    const float* wq    = (const float*)d_in[3];
    const float* bq    = (const float*)d_in[4];
    const float* wk    = (const float*)d_in[5];
    const float* bk    = (const float*)d_in[6];
    const float* wv    = (const float*)d_in[7];
    const float* bv    = (const float*)d_in[8];
    const float* wo    = (const float*)d_in[9];
    const float* bo    = (const float*)d_in[10];
    float* out = (float*)d_out;

    cudaFuncSetAttribute(qkv_kernel, cudaFuncAttributeMaxDynamicSharedMemorySize, SMEM_BYTES);
    cudaFuncSetAttribute(score_vp_kernel, cudaFuncAttributeMaxDynamicSharedMemorySize, SMEM_BYTES);
    cudaFuncSetAttribute(sv_kernel, cudaFuncAttributeMaxDynamicSharedMemorySize, SMEM_BYTES);

    // 0) prep: weights->bf16, biases, GN stats (single launch)
    prep_kernel<<<1030 + BB * GG, 256>>>(wq, wk, wv, wo, bq, bk, bv, x);

    // 1) normalize + transpose
    gn_norm_t_kernel<<<dim3(HWN / 32, CC / 32, BB), dim3(32, 8)>>>(x, gamma, beta);

    // 2) fused QKV projection
    qkv_kernel<<<dim3(3 * CC / BN, BB * HWN / BM, 1), 256, SMEM_BYTES>>>();

    // 3) merged: scores (+exp,+psum)  AND  V' = V@Wo^T (transposed)
    score_vp_kernel<<<dim3(NTILES + CC / BN, HWN / BM, BB), 256, SMEM_BYTES>>>();

    // 4) out = (P @ V')*rinv + bo + resid -> f32 [b][c][hw]
    sv_kernel<<<dim3(CC / BN, HWN / BM, BB), 256, SMEM_BYTES>>>(bo, x, out);
}

// round 15
// speedup vs baseline: 1.0707x; 1.0276x over previous
#include <cuda_runtime.h>
#include <cuda.h>
#include <cuda_bf16.h>
#include <math.h>
#include <stdint.h>

// Problem constants
#define CC   512
#define HWN  4096
#define BB   8
#define GG   32
#define CPG  16
#define EPSF 1e-6f
#define ALPHAF 0.044194173824159216f
#define ALPHA_LOG2E 0.06376059f        // ALPHAF * log2(e)

// GEMM tiling (bf16): 128x128 tile, 3 stages, 2 CTAs/SM
#define BM 128
#define BN 128
#define KC 64
#define STAGES 3
#define PITCHB  144
#define STG_BYTES ((BM + BN) * PITCHB) // 36864
#define SMEM_BYTES (STAGES * STG_BYTES)  // 110592
#define TRB_PITCH 136
#define TRF_PITCH 132

#define REG_SZ (BB * HWN * CC)
#define NTILES (HWN / BN)              // 32 scores n-tiles

typedef __nv_bfloat16 bf16;
typedef __nv_bfloat162 bf162;

// ---------------------------------------------------------------------------
// Device-global scratch
// ---------------------------------------------------------------------------
__device__ bf16 g_h[BB * HWN * CC];
__device__ bf16 g_qkv[3 * REG_SZ];             // q | k | v row-major [b][n][c]
__device__ bf16 g_vpt[REG_SZ];                 // V' = V@Wo^T transposed [b][c][n]
__device__ bf16 g_s[(size_t)BB * HWN * HWN];   // unnorm probs (256MB)
__device__ bf16 g_w[4 * CC * CC];              // wq|wk|wv|wo
__device__ float g_bqkv[3 * CC];
__device__ float g_psum[(size_t)BB * NTILES * HWN];
__device__ float g_mu[BB * GG];
__device__ float g_rstd[BB * GG];

// ---------------------------------------------------------------------------
// Helpers
// ---------------------------------------------------------------------------
__device__ __forceinline__ uint32_t smem_u32(const void* p) {
    uint32_t a;
    asm("{ .reg .u64 t; cvta.to.shared.u64 t, %1; cvt.u32.u64 %0, t; }"
        : "=r"(a) : "l"(p));
    return a;
}
__device__ __forceinline__ void cp_async16(uint32_t dst, const void* src) {
    asm volatile("cp.async.cg.shared.global [%0], [%1], 16;" :: "r"(dst), "l"(src));
}
__device__ __forceinline__ void cp_commit() {
    asm volatile("cp.async.commit_group;");
}
__device__ __forceinline__ void mma_bf16(float* d, const uint32_t* a, const uint32_t* b) {
    asm volatile(
        "mma.sync.aligned.m16n8k16.row.col.f32.bf16.bf16.f32 "
        "{%0,%1,%2,%3},{%4,%5,%6,%7},{%8,%9},{%0,%1,%2,%3};"
        : "+f"(d[0]), "+f"(d[1]), "+f"(d[2]), "+f"(d[3])
        : "r"(a[0]), "r"(a[1]), "r"(a[2]), "r"(a[3]), "r"(b[0]), "r"(b[1]));
}
#define LDSM4(r0, r1, r2, r3, addr) \
    asm volatile("ldmatrix.sync.aligned.m8n8.x4.shared.b16 {%0,%1,%2,%3}, [%4];" \
        : "=r"(r0), "=r"(r1), "=r"(r2), "=r"(r3) : "r"(addr))

__device__ __forceinline__ uint32_t pack2(float x, float y) {
    bf162 h = __floats2bfloat162_rn(x, y);
    return *reinterpret_cast<uint32_t*>(&h);
}

// ---------------------------------------------------------------------------
// Shared mainloop body (128x128 tile, K-major bf16 operands).
// Chunk loop restructured: rolled outer += 3, unrolled inner x3 so the
// smem stage index is a COMPILE-TIME constant (no % STAGES in the hot path).
// ---------------------------------------------------------------------------
struct Frag { float acc[4][4][4]; };

__device__ __forceinline__ void load_chunk(
    const bf16* __restrict__ A, const bf16* __restrict__ Bm,
    int m0, int n0, int lda, int ldb, int k0, uint32_t sb, int tid)
{
    #pragma unroll
    for (int i = 0; i < 4; i++) {
        int idx = i * 256 + tid;
        int row = idx >> 3, kq = idx & 7;
        cp_async16(sb + row * PITCHB + kq * 16,
                   A + (size_t)(m0 + row) * lda + k0 + kq * 8);
    }
    #pragma unroll
    for (int i = 0; i < 4; i++) {
        int idx = i * 256 + tid;
        int row = idx >> 3, kq = idx & 7;
        cp_async16(sb + BM * PITCHB + row * PITCHB + kq * 16,
                   Bm + (size_t)(n0 + row) * ldb + k0 + kq * 8);
    }
    cp_commit();
}

__device__ __forceinline__ void compute_chunk(
    uint32_t sb, const uint32_t* aoff, const uint32_t* boff, Frag& f)
{
    #pragma unroll
    for (int ks = 0; ks < 4; ks++) {
        const uint32_t kb = sb + ks * 32;
        uint32_t af[4][4];
        #pragma unroll
        for (int mt = 0; mt < 4; mt++)
            LDSM4(af[mt][0], af[mt][1], af[mt][2], af[mt][3], kb + aoff[mt]);
        uint32_t bfm[4][2];
        #pragma unroll
        for (int p = 0; p < 2; p++)
            LDSM4(bfm[2 * p][0], bfm[2 * p][1], bfm[2 * p + 1][0], bfm[2 * p + 1][1],
                  kb + boff[p]);
        #pragma unroll
        for (int mt = 0; mt < 4; mt++)
            #pragma unroll
            for (int nt = 0; nt < 4; nt++)
                mma_bf16(f.acc[mt][nt], af[mt], bfm[nt]);
    }
}

__device__ __forceinline__ void gemm_mainloop_512(
    const bf16* __restrict__ A, const bf16* __restrict__ Bm,
    int m0, int n0, int lda, int ldb, int NC,
    uint32_t smem_base, const uint32_t* aoff, const uint32_t* boff,
    int tid, Frag& f)
{
    #pragma unroll
    for (int mt = 0; mt < 4; mt++)
        #pragma unroll
        for (int nt = 0; nt < 4; nt++)
            #pragma unroll
            for (int c = 0; c < 4; c++) f.acc[mt][nt][c] = 0.f;

    // prefetch stages 0, 1 (compile-time stage offsets)
    load_chunk(A, Bm, m0, n0, lda, ldb, 0 * KC, smem_base + 0 * STG_BYTES, tid);
    load_chunk(A, Bm, m0, n0, lda, ldb, 1 * KC, smem_base + 1 * STG_BYTES, tid);

    for (int cb = 0; cb < NC; cb += 3) {
        #pragma unroll
        for (int u = 0; u < 3; u++) {
            const int c = cb + u;
            if (c < NC) {
                asm volatile("cp.async.wait_group %0;" :: "n"(STAGES - 2));
                __syncthreads();
                const int pf = c + 2;
                if (pf < NC) {
                    // stage (u+2)%3 is a compile-time constant per unrolled body
                    const uint32_t sb_in =
                        smem_base + ((u + 2) % 3) * STG_BYTES;
                    load_chunk(A, Bm, m0, n0, lda, ldb, pf * KC, sb_in, tid);
                }
                compute_chunk(smem_base + u * STG_BYTES, aoff, boff, f);
            }
        }
    }
}

#define THREAD_IDS \
    const int tid = threadIdx.x; \
    const int wid = tid >> 5; \
    const int lane = tid & 31; \
    const int g = lane >> 2; \
    const int kin = lane & 3; \
    const int wm = wid & 1; \
    const int wn = wid >> 1; \
    const int lq = lane >> 3; \
    const int lr = lane & 7; \
    uint32_t aoff[4], boff[2]; \
    _Pragma("unroll") \
    for (int mt = 0; mt < 4; mt++) \
        aoff[mt] = (uint32_t)((wm * 64 + mt * 16 + (lq & 1) * 8 + lr) * PITCHB \
                              + (lq >> 1) * 16); \
    _Pragma("unroll") \
    for (int p = 0; p < 2; p++) \
        boff[p] = (uint32_t)(BM * PITCHB \
                             + (wn * 32 + (2 * p + (lq >> 1)) * 8 + lr) * PITCHB \
                             + (lq & 1) * 16);

// ---------------------------------------------------------------------------
// Merged scores + V' kernel.
//   blockIdx.x < 32 : scores tile  S[z] = exp2(a * Q K^T), psum
//   blockIdx.x >= 32: V' tile      g_vpt[z][ch][tok] = (V @ Wo^T)^T
// ---------------------------------------------------------------------------
__global__ void __launch_bounds__(256, 2)
score_vp_kernel()
{
    extern __shared__ char smem[];
    const uint32_t smem_base = smem_u32(smem);
    THREAD_IDS;

    const int z = blockIdx.z;
    const bool is_vp = (blockIdx.x >= NTILES);
    const int m0 = blockIdx.y * BM;
    int n0;
    const bf16 *A, *Bm;
    if (!is_vp) {
        n0 = blockIdx.x * BN;
        A  = g_qkv + (size_t)z * HWN * CC;
        Bm = g_qkv + REG_SZ + (size_t)z * HWN * CC;
    } else {
        n0 = (blockIdx.x - NTILES) * BN;
        A  = g_qkv + 2 * (size_t)REG_SZ + (size_t)z * HWN * CC;
        Bm = g_w + 3 * CC * CC;
    }

    Frag f;
    gemm_mainloop_512(A, Bm, m0, n0, CC, CC, CC / KC, smem_base, aoff, boff, tid, f);

    if (!is_vp) {
        bf16* Cout = g_s + (size_t)z * HWN * HWN;
        __syncthreads();
        float (*sm)[5] = (float(*)[5])smem;
        #pragma unroll
        for (int mt = 0; mt < 4; mt++) {
            int rl = wm * 64 + mt * 16 + g;
            int r0 = m0 + rl;
            float s0 = 0.f, s1 = 0.f;
            #pragma unroll
            for (int nt = 0; nt < 4; nt++) {
                int ch = n0 + wn * 32 + nt * 8 + kin * 2;
                float e0 = exp2f(ALPHA_LOG2E * f.acc[mt][nt][0]);
                float e1 = exp2f(ALPHA_LOG2E * f.acc[mt][nt][1]);
                float e2 = exp2f(ALPHA_LOG2E * f.acc[mt][nt][2]);
                float e3 = exp2f(ALPHA_LOG2E * f.acc[mt][nt][3]);
                *(bf162*)(Cout + (size_t)r0 * HWN + ch) = __floats2bfloat162_rn(e0, e1);
                *(bf162*)(Cout + (size_t)(r0 + 8) * HWN + ch) = __floats2bfloat162_rn(e2, e3);
                s0 += e0 + e1;
                s1 += e2 + e3;
            }
            s0 += __shfl_xor_sync(0xffffffffu, s0, 1);
            s0 += __shfl_xor_sync(0xffffffffu, s0, 2);
            s1 += __shfl_xor_sync(0xffffffffu, s1, 1);
            s1 += __shfl_xor_sync(0xffffffffu, s1, 2);
            if (kin == 0) {
                sm[rl][wn] = s0;
                sm[rl + 8][wn] = s1;
            }
        }
        __syncthreads();
        if (tid < 128) {
            float t = sm[tid][0] + sm[tid][1] + sm[tid][2] + sm[tid][3];
            g_psum[((size_t)z * NTILES + blockIdx.x) * HWN + m0 + tid] = t;
        }
    } else {
        // V' transposed bf16 store -> g_vpt[z][ch][tok]
        __syncthreads();
        bf16* tr = (bf16*)smem;
        #pragma unroll
        for (int mt = 0; mt < 4; mt++) {
            int tok = wm * 64 + mt * 16 + g;
            #pragma unroll
            for (int nt = 0; nt < 4; nt++) {
                int cl = wn * 32 + nt * 8 + kin * 2;
                tr[(cl    ) * TRB_PITCH + tok    ] = __float2bfloat16_rn(f.acc[mt][nt][0]);
                tr[(cl + 1) * TRB_PITCH + tok    ] = __float2bfloat16_rn(f.acc[mt][nt][1]);
                tr[(cl    ) * TRB_PITCH + tok + 8] = __float2bfloat16_rn(f.acc[mt][nt][2]);
                tr[(cl + 1) * TRB_PITCH + tok + 8] = __float2bfloat16_rn(f.acc[mt][nt][3]);
            }
        }
        __syncthreads();
        #pragma unroll
        for (int i = 0; i < 8; i++) {
            int idx = i * 256 + tid;
            int cl = idx >> 4, t8 = (idx & 15) * 8;
            uint4 v = *(uint4*)&tr[cl * TRB_PITCH + t8];
            *(uint4*)(g_vpt + ((size_t)z * CC + n0 + cl) * HWN + m0 + t8) = v;
        }
    }
}

// ---------------------------------------------------------------------------
// QKV kernel: C = h @ [wq|wk|wv]^T + bias, row-major bf16
// ---------------------------------------------------------------------------
__global__ void __launch_bounds__(256, 2)
qkv_kernel()
{
    extern __shared__ char smem[];
    const uint32_t smem_base = smem_u32(smem);
    THREAD_IDS;

    const int m0 = blockIdx.y * BM;
    const int n0 = blockIdx.x * BN;        // 0..1535

    Frag f;
    gemm_mainloop_512(g_h, g_w, m0, n0, CC, CC, CC / KC, smem_base, aoff, boff, tid, f);

    const int which = n0 >> 9;
    bf16* Cout = g_qkv + (size_t)which * REG_SZ;
    const int nsub0 = n0 & 511;
    #pragma unroll
    for (int mt = 0; mt < 4; mt++) {
        int r0 = m0 + wm * 64 + mt * 16 + g;
        #pragma unroll
        for (int nt = 0; nt < 4; nt++) {
            int cl = wn * 32 + nt * 8 + kin * 2;
            float b0 = g_bqkv[n0 + cl], b1 = g_bqkv[n0 + cl + 1];
            int ch = nsub0 + cl;
            *(bf162*)(Cout + (size_t)r0 * CC + ch) =
                __floats2bfloat162_rn(f.acc[mt][nt][0] + b0, f.acc[mt][nt][1] + b1);
            *(bf162*)(Cout + (size_t)(r0 + 8) * CC + ch) =
                __floats2bfloat162_rn(f.acc[mt][nt][2] + b0, f.acc[mt][nt][3] + b1);
        }
    }
}

// ---------------------------------------------------------------------------
// SV final kernel: out = (P @ V')*rinv + bo + resid, f32 [b][c][hw]
// ---------------------------------------------------------------------------
__global__ void __launch_bounds__(256, 2)
sv_kernel(const float* __restrict__ bias, const float* __restrict__ resid,
          float* __restrict__ Cout)
{
    extern __shared__ char smem[];
    const uint32_t smem_base = smem_u32(smem);
    THREAD_IDS;

    const int z = blockIdx.z;
    const int m0 = blockIdx.y * BM;
    const int n0 = blockIdx.x * BN;
    const bf16* A  = g_s + (size_t)z * HWN * HWN;
    const bf16* Bm = g_vpt + (size_t)z * CC * HWN;

    Frag f;
    gemm_mainloop_512(A, Bm, m0, n0, HWN, HWN, HWN / KC, smem_base, aoff, boff, tid, f);

    __syncthreads();
    float* rsh = (float*)smem;
    if (tid < 128) {
        const float* p = g_psum + (size_t)z * NTILES * HWN + m0 + tid;
        float s = 0.f;
        #pragma unroll
        for (int t = 0; t < NTILES; t++) s += p[(size_t)t * HWN];
        rsh[tid] = 1.f / s;
    }
    __syncthreads();
    float iv[4][2];
    #pragma unroll
    for (int mt = 0; mt < 4; mt++) {
        int rl = wm * 64 + mt * 16 + g;
        iv[mt][0] = rsh[rl];
        iv[mt][1] = rsh[rl + 8];
    }
    __syncthreads();
    float* tr = (float*)smem;
    #pragma unroll
    for (int mt = 0; mt < 4; mt++) {
        int tok = wm * 64 + mt * 16 + g;
        #pragma unroll
        for (int nt = 0; nt < 4; nt++) {
            int ch = wn * 32 + nt * 8 + kin * 2;
            tr[(ch    ) * TRF_PITCH + tok    ] = f.acc[mt][nt][0] * iv[mt][0];
            tr[(ch + 1) * TRF_PITCH + tok    ] = f.acc[mt][nt][1] * iv[mt][0];
            tr[(ch    ) * TRF_PITCH + tok + 8] = f.acc[mt][nt][2] * iv[mt][1];
            tr[(ch + 1) * TRF_PITCH + tok + 8] = f.acc[mt][nt][3] * iv[mt][1];
        }
    }
    __syncthreads();
    #pragma unroll
    for (int i = 0; i < 16; i++) {
        int idx = i * 256 + tid;
        int ch = idx >> 5, t4 = (idx & 31) * 4;
        float4 v = *(float4*)&tr[ch * TRF_PITCH + t4];
        float bv = bias[n0 + ch];
        v.x += bv; v.y += bv; v.z += bv; v.w += bv;
        size_t oidx = ((size_t)z * CC + n0 + ch) * HWN + m0 + t4;
        float4 rr = *(const float4*)(resid + oidx);
        v.x += rr.x; v.y += rr.y; v.z += rr.z; v.w += rr.w;
        *(float4*)(Cout + oidx) = v;
    }
}

// ---------------------------------------------------------------------------
// Prep kernel: weights->bf16 (blocks 0..1023), biases (1024..1029),
// GN stats (1030..1285)
// ---------------------------------------------------------------------------
__global__ void prep_kernel(const float* __restrict__ wq, const float* __restrict__ wk,
                            const float* __restrict__ wv, const float* __restrict__ wo,
                            const float* __restrict__ bq, const float* __restrict__ bk,
                            const float* __restrict__ bv, const float* __restrict__ x) {
    __shared__ float sh1[256], sh2[256];
    const int blk = blockIdx.x;
    if (blk < 1024) {
        int i = (blk * 256 + threadIdx.x) * 4;
        int w = i >> 18;
        const float* s = (w == 0) ? wq : (w == 1) ? wk : (w == 2) ? wv : wo;
        float4 v = *(const float4*)(s + (i & (CC * CC - 1)));
        uint2 o;
        o.x = pack2(v.x, v.y);
        o.y = pack2(v.z, v.w);
        *(uint2*)(g_w + i) = o;
    } else if (blk < 1030) {
        int i = (blk - 1024) * 256 + threadIdx.x;
        const float* src = (i < CC) ? bq : (i < 2 * CC) ? bk : bv;
        g_bqkv[i] = src[i & (CC - 1)];
    } else {
        const int bg = blk - 1030;
        const int b = bg / GG, g = bg % GG;
        const float4* xp = (const float4*)(x + ((size_t)b * CC + (size_t)g * CPG) * HWN);
        float s = 0.f, ss = 0.f;
        #pragma unroll 4
        for (int i = threadIdx.x; i < CPG * HWN / 4; i += 256) {
            float4 v = xp[i];
            s  += v.x + v.y + v.z + v.w;
            ss += v.x * v.x + v.y * v.y + v.z * v.z + v.w * v.w;
        }
        sh1[threadIdx.x] = s; sh2[threadIdx.x] = ss;
        __syncthreads();
        for (int o = 128; o > 0; o >>= 1) {
            if (threadIdx.x < o) {
                sh1[threadIdx.x] += sh1[threadIdx.x + o];
                sh2[threadIdx.x] += sh2[threadIdx.x + o];
            }
            __syncthreads();
        }
        if (threadIdx.x == 0) {
            const float inv_n = 1.f / (CPG * HWN);
            float mu = sh1[0] * inv_n;
            float var = sh2[0] * inv_n - mu * mu;
            g_mu[bg] = mu;
            g_rstd[bg] = rsqrtf(var + EPSF);
        }
    }
}

// ---------------------------------------------------------------------------
// Normalize + transpose -> h[b][n][c] bf16.
// v2: 64-channel tiles so g_h stores are full 128-byte rows (bf162-packed).
// grid (HWN/32, CC/64, BB), block (32, 8).
// ---------------------------------------------------------------------------
__global__ void gn_norm_t_kernel(const float* __restrict__ x,
                                 const float* __restrict__ gamma,
                                 const float* __restrict__ beta) {
    __shared__ float tile[64][33];
    const int b = blockIdx.z;
    const int n0 = blockIdx.x * 32;
    const int c0 = blockIdx.y * 64;
    #pragma unroll
    for (int i = 0; i < 8; i++) {
        int cl = threadIdx.y + i * 8;
        int c = c0 + cl;
        float v = x[((size_t)b * CC + c) * HWN + n0 + threadIdx.x];
        int gidx = b * GG + (c / CPG);
        v = (v - g_mu[gidx]) * g_rstd[gidx] * gamma[c] + beta[c];
        tile[cl][threadIdx.x] = v;
    }
    __syncthreads();
    const int tid = threadIdx.y * 32 + threadIdx.x;
    #pragma unroll
    for (int i = 0; i < 4; i++) {
        int flat = i * 256 + tid;
        int nl = flat >> 5;          // 0..31
        int cp = flat & 31;          // bf162 index
        uint32_t v = pack2(tile[cp * 2][nl], tile[cp * 2 + 1][nl]);
        *(uint32_t*)(g_h + ((size_t)b * HWN + n0 + nl) * CC + c0 + cp * 2) = v;
    }
}

// ---------------------------------------------------------------------------
// Launch
// ---------------------------------------------------------------------------
extern "C" void kernel_launch(void* const* d_in, const int* in_sizes, int n_in,
                              void* d_out, int out_size) {
    const float* x     = (const float*)d_in[0];
    const float* gamma = (const float*)d_in[1];
    const float* beta  = (const float*)d_in[2];
    const float* wq    = (const float*)d_in[3];
    const float* bq    = (const float*)d_in[4];
    const float* wk    = (const float*)d_in[5];
    const float* bk    = (const float*)d_in[6];
    const float* wv    = (const float*)d_in[7];
    const float* bv    = (const float*)d_in[8];
    const float* wo    = (const float*)d_in[9];
    const float* bo    = (const float*)d_in[10];
    float* out = (float*)d_out;

    cudaFuncSetAttribute(qkv_kernel, cudaFuncAttributeMaxDynamicSharedMemorySize, SMEM_BYTES);
    cudaFuncSetAttribute(score_vp_kernel, cudaFuncAttributeMaxDynamicSharedMemorySize, SMEM_BYTES);
    cudaFuncSetAttribute(sv_kernel, cudaFuncAttributeMaxDynamicSharedMemorySize, SMEM_BYTES);

    // 0) prep: weights->bf16, biases, GN stats (single launch)
    prep_kernel<<<1030 + BB * GG, 256>>>(wq, wk, wv, wo, bq, bk, bv, x);

    // 1) normalize + transpose
    gn_norm_t_kernel<<<dim3(HWN / 32, CC / 64, BB), dim3(32, 8)>>>(x, gamma, beta);

    // 2) fused QKV projection
    qkv_kernel<<<dim3(3 * CC / BN, BB * HWN / BM, 1), 256, SMEM_BYTES>>>();

    // 3) merged: scores (+exp,+psum)  AND  V' = V@Wo^T (transposed)
    score_vp_kernel<<<dim3(NTILES + CC / BN, HWN / BM, BB), 256, SMEM_BYTES>>>();

    // 4) out = (P @ V')*rinv + bo + resid -> f32 [b][c][hw]
    sv_kernel<<<dim3(CC / BN, HWN / BM, BB), 256, SMEM_BYTES>>>(bo, x, out);
}